// round 11
// baseline (speedup 1.0000x reference)
#include <cuda_runtime.h>
#include <cuda_fp16.h>
#include <stdint.h>

#define B_ 256
#define R_ 192
#define C_ 96
#define O_ 16
#define I_ 20
#define IP 24                   // I padded for mma (zeros)
#define BCH 8                   // batch elements per tile
#define NCH (B_ / BCH)          // 32 chunks
#define TILES (C_ * NCH)        // 3072
#define GRID 304                // persistent CTAs (2/SM on 152 SMs)
#define TILE_U4 (R_ * BCH * O_ / 8)   // 3072 uint4 = 48KB per tile
#define TILE_HALFS (R_ * BCH * O_)    // 24576 halves
#define TILE_BYTES (TILE_U4 * 16)     // 49152

// Scratch (allocation-free rule: __device__ globals)
__device__ uint4  g_uhat4[(size_t)TILES * TILE_U4];   // tile-contiguous u_hat fp16
__device__ __half g_x16[(size_t)R_ * B_ * IP];        // x fp16 [r][b][24]
__device__ __half g_W16[(size_t)R_ * C_ * O_ * IP];   // W fp16 [r][c][o][24]
__device__ float  g_part[2][C_][R_][NCH];             // agreement partials
__device__ float  g_c[C_ * R_];                       // softmax coefficients [c][r]

// ---- smem addr / TMA bulk / mbarrier helpers ----
__device__ __forceinline__ uint32_t smem_u32(const void* p) {
    return (uint32_t)__cvta_generic_to_shared(p);
}
__device__ __forceinline__ void mbar_init(uint32_t mbar, uint32_t cnt) {
    asm volatile("mbarrier.init.shared.b64 [%0], %1;" :: "r"(mbar), "r"(cnt)
                 : "memory");
}
__device__ __forceinline__ void mbar_expect_tx(uint32_t mbar, uint32_t bytes) {
    asm volatile("mbarrier.arrive.expect_tx.shared.b64 _, [%0], %1;"
                 :: "r"(mbar), "r"(bytes) : "memory");
}
__device__ __forceinline__ void mbar_wait(uint32_t mbar, uint32_t parity) {
    asm volatile(
        "{\n\t.reg .pred P;\n\t"
        "WL%=:\n\t"
        "mbarrier.try_wait.parity.acquire.cta.shared::cta.b64 P, [%0], %1, 0x989680;\n\t"
        "@!P bra WL%=;\n\t}"
        :: "r"(mbar), "r"(parity) : "memory");
}
__device__ __forceinline__ void fence_proxy_async_cta() {
    asm volatile("fence.proxy.async.shared::cta;" ::: "memory");
}
__device__ __forceinline__ void bulk_copy_g2s(uint32_t dst, const void* src,
                                              uint32_t bytes, uint32_t mbar) {
    asm volatile(
        "cp.async.bulk.shared::cta.global.mbarrier::complete_tx::bytes "
        "[%0], [%1], %2, [%3];"
        :: "r"(dst), "l"(src), "r"(bytes), "r"(mbar) : "memory");
}

// ---- ldmatrix helpers ----
__device__ __forceinline__ void ldsm4(uint32_t& r0, uint32_t& r1, uint32_t& r2,
                                      uint32_t& r3, uint32_t addr) {
    asm volatile("ldmatrix.sync.aligned.m8n8.x4.shared.b16 {%0,%1,%2,%3}, [%4];"
                 : "=r"(r0), "=r"(r1), "=r"(r2), "=r"(r3) : "r"(addr));
}
__device__ __forceinline__ void ldsm4t(uint32_t& r0, uint32_t& r1, uint32_t& r2,
                                       uint32_t& r3, uint32_t addr) {
    asm volatile("ldmatrix.sync.aligned.m8n8.x4.trans.shared.b16 {%0,%1,%2,%3}, [%4];"
                 : "=r"(r0), "=r"(r1), "=r"(r2), "=r"(r3) : "r"(addr));
}

// ---- mma helpers (fp16 in, fp32 accum) ----
__device__ __forceinline__ void mma16816(float d[4], uint32_t a0, uint32_t a1,
                                         uint32_t a2, uint32_t a3,
                                         uint32_t b0, uint32_t b1) {
    asm volatile(
        "mma.sync.aligned.m16n8k16.row.col.f32.f16.f16.f32 "
        "{%0,%1,%2,%3},{%4,%5,%6,%7},{%8,%9},{%0,%1,%2,%3};"
        : "+f"(d[0]), "+f"(d[1]), "+f"(d[2]), "+f"(d[3])
        : "r"(a0), "r"(a1), "r"(a2), "r"(a3), "r"(b0), "r"(b1));
}
__device__ __forceinline__ void mma1688(float d[4], uint32_t a0, uint32_t a1,
                                        uint32_t b0) {
    asm volatile(
        "mma.sync.aligned.m16n8k8.row.col.f32.f16.f16.f32 "
        "{%0,%1,%2,%3},{%4,%5},{%6},{%0,%1,%2,%3};"
        : "+f"(d[0]), "+f"(d[1]), "+f"(d[2]), "+f"(d[3])
        : "r"(a0), "r"(a1), "r"(b0));
}

// ============================================================================
// Convert x[b][r][i] f32 -> x16[r][b][24] fp16 (i padded with zeros).
// ============================================================================
__global__ void convx_kernel(const float* __restrict__ x) {
    const int r = blockIdx.x;
    const int b = threadIdx.x;
    const float4* src = reinterpret_cast<const float4*>(x + ((size_t)b * R_ + r) * I_);
    __half2 h[12];
#pragma unroll
    for (int q = 0; q < 5; q++) {
        float4 v = src[q];
        h[2 * q]     = __floats2half2_rn(v.x, v.y);
        h[2 * q + 1] = __floats2half2_rn(v.z, v.w);
    }
    h[10] = __floats2half2_rn(0.f, 0.f);
    h[11] = __floats2half2_rn(0.f, 0.f);
    uint4* dst = reinterpret_cast<uint4*>(g_x16 + ((size_t)r * B_ + b) * IP);
    dst[0] = *reinterpret_cast<uint4*>(&h[0]);
    dst[1] = *reinterpret_cast<uint4*>(&h[4]);
    dst[2] = *reinterpret_cast<uint4*>(&h[8]);
}

// ============================================================================
// Convert W[r][c][o][i] f32 -> W16[r][c][o][24] fp16 (padded).
// ============================================================================
__global__ void convw_kernel(const float* __restrict__ W) {
    const int idx = blockIdx.x * 256 + threadIdx.x;   // (r,c,o) flat, 294912
    const float4* src = reinterpret_cast<const float4*>(W + (size_t)idx * I_);
    __half2 h[12];
#pragma unroll
    for (int q = 0; q < 5; q++) {
        float4 v = src[q];
        h[2 * q]     = __floats2half2_rn(v.x, v.y);
        h[2 * q + 1] = __floats2half2_rn(v.z, v.w);
    }
    h[10] = __floats2half2_rn(0.f, 0.f);
    h[11] = __floats2half2_rn(0.f, 0.f);
    uint4* dst = reinterpret_cast<uint4*>(g_W16 + (size_t)idx * IP);
    dst[0] = *reinterpret_cast<uint4*>(&h[0]);
    dst[1] = *reinterpret_cast<uint4*>(&h[4]);
    dst[2] = *reinterpret_cast<uint4*>(&h[8]);
}

// ============================================================================
// u_hat via tensor cores. Block = (r, 8 c's), 256 threads = 8 warps (1 c each).
// ============================================================================
__global__ void __launch_bounds__(256) uhat_mma_kernel() {
    const int r  = blockIdx.x / (C_ / 8);
    const int c0 = (blockIdx.x % (C_ / 8)) * 8;
    __shared__ __align__(16) __half xs[B_ * IP];      // [b][24]  12288B
    __shared__ __align__(16) __half ws[8 * O_ * IP];  // [cc][o][24] 6144B
    const int tid = threadIdx.x;
    const int lane = tid & 31, w = tid >> 5;

    {
        const uint4* gx = reinterpret_cast<const uint4*>(g_x16 + (size_t)r * B_ * IP);
        uint4* sx = reinterpret_cast<uint4*>(xs);
#pragma unroll
        for (int m = 0; m < 3; m++) sx[tid + 256 * m] = gx[tid + 256 * m];
        const uint4* gw = reinterpret_cast<const uint4*>(
            g_W16 + ((size_t)r * C_ + c0) * O_ * IP);
        uint4* sw = reinterpret_cast<uint4*>(ws);
        if (tid < 128) { sw[tid] = gw[tid]; sw[tid + 128] = gw[tid + 128]; }
        else { int t = tid - 128; sw[t + 256] = gw[t + 256]; }
    }
    __syncthreads();

    const uint32_t* xs32 = reinterpret_cast<const uint32_t*>(xs);
    const uint32_t* ws32 = reinterpret_cast<const uint32_t*>(ws);
    __half* uh = reinterpret_cast<__half*>(g_uhat4);

    uint32_t bf[2][3];
#pragma unroll
    for (int nt = 0; nt < 2; nt++) {
        int base = (w * 16 + nt * 8 + (lane >> 2)) * 12 + (lane & 3);
        bf[nt][0] = ws32[base];
        bf[nt][1] = ws32[base + 4];
        bf[nt][2] = ws32[base + 8];
    }

    const int c = c0 + w;
#pragma unroll 4
    for (int bt = 0; bt < 16; bt++) {
        const int row = bt * 16 + (lane >> 2);
        const int a0i = row * 12 + (lane & 3);
        const int a1i = a0i + 96;   // row + 8
        uint32_t a0 = xs32[a0i], a1 = xs32[a1i];
        uint32_t a2 = xs32[a0i + 4], a3 = xs32[a1i + 4];
        uint32_t a4 = xs32[a0i + 8], a5 = xs32[a1i + 8];

#pragma unroll
        for (int nt = 0; nt < 2; nt++) {
            float d[4] = {0.f, 0.f, 0.f, 0.f};
            mma16816(d, a0, a1, a2, a3, bf[nt][0], bf[nt][1]);
            mma1688(d, a4, a5, bf[nt][2]);
            __half2 h01 = __floats2half2_rn(d[0], d[1]);
            __half2 h23 = __floats2half2_rn(d[2], d[3]);
            const int o2 = nt * 8 + (lane & 3) * 2;
            const int blo = row, bhi = row + 8;
            size_t alo = ((size_t)(c * NCH + (blo >> 3))) * TILE_HALFS
                       + (size_t)r * 128 + (blo & 7) * 16 + o2;
            size_t ahi = ((size_t)(c * NCH + (bhi >> 3))) * TILE_HALFS
                       + (size_t)r * 128 + (bhi & 7) * 16 + o2;
            *reinterpret_cast<__half2*>(uh + alo) = h01;
            *reinterpret_cast<__half2*>(uh + ahi) = h23;
        }
    }
}

// ============================================================================
// Softmax over r of accumulated logits -> g_c[c][r]. One block per c.
// ============================================================================
__global__ void softmax_kernel(int it) {
    const int c = blockIdx.x;
    const int tid = threadIdx.x;           // = r
    const int lane = tid & 31, warp = tid >> 5;
    __shared__ float sm[6], ssum[6];

    float lg = 0.f;
    {
        const float4* q0 = reinterpret_cast<const float4*>(&g_part[0][c][tid][0]);
#pragma unroll
        for (int j = 0; j < NCH / 4; j++) {
            float4 v = q0[j];
            lg += v.x + v.y + v.z + v.w;
        }
        if (it == 2) {
            const float4* q1 = reinterpret_cast<const float4*>(&g_part[1][c][tid][0]);
#pragma unroll
            for (int j = 0; j < NCH / 4; j++) {
                float4 v = q1[j];
                lg += v.x + v.y + v.z + v.w;
            }
        }
        lg *= (1.f / B_);
    }

    float m = lg;
#pragma unroll
    for (int ofs = 16; ofs; ofs >>= 1) m = fmaxf(m, __shfl_xor_sync(0xFFFFFFFFu, m, ofs));
    if (lane == 0) sm[warp] = m;
    __syncthreads();
    float mm = sm[0];
#pragma unroll
    for (int w = 1; w < 6; w++) mm = fmaxf(mm, sm[w]);

    float e = expf(lg - mm);
    float s = e;
#pragma unroll
    for (int ofs = 16; ofs; ofs >>= 1) s += __shfl_xor_sync(0xFFFFFFFFu, s, ofs);
    if (lane == 0) ssum[warp] = s;
    __syncthreads();
    float tot = 0.f;
#pragma unroll
    for (int w = 0; w < 6; w++) tot += ssum[w];

    g_c[c * R_ + tid] = e / tot;
}

// ============================================================================
// Persistent fused routing kernel. 304 CTAs x 512 threads, double-buffered
// 48KB tiles via cp.async.bulk + mbarrier. Phases 1 & 2 run on tensor cores:
//   phase1: s[bo] = sum_r c[r]*u[r][bo]   (mma, A via ldmatrix.trans)
//   phase2: a[r]  = sum_bo u[r][bo]*v[bo] (mma, A via ldmatrix)
// ============================================================================
__global__ void __launch_bounds__(512, 2) fused_kernel(float* __restrict__ out, int it) {
    extern __shared__ __align__(16) uint4 su4[];   // 2 * TILE_U4
    __shared__ float   sred[2][128];               // per-k-half s partials
    __shared__ __half2 sv_h[64];                   // v fp16 pairs [bo/2]
    __shared__ __half2 sch[96];                    // c fp16 pairs [r/2]
    __shared__ __align__(8) uint64_t mbars[2];

    const int tid = threadIdx.x;
    const int lane = tid & 31, warp = tid >> 5;    // 16 warps
    const uint32_t mb0 = smem_u32(&mbars[0]);
    const uint32_t mb1 = smem_u32(&mbars[1]);
    const uint32_t sbase = smem_u32(su4);

    if (tid == 0) {
        mbar_init(mb0, 1);
        mbar_init(mb1, 1);
        fence_proxy_async_cta();
    }
    __syncthreads();

    // ---- prologue: issue first tile into buffer 0 ----
    if (tid == 0) {
        mbar_expect_tx(mb0, TILE_BYTES);
        bulk_copy_g2s(sbase, g_uhat4 + (size_t)blockIdx.x * TILE_U4,
                      TILE_BYTES, mb0);
    }

    uint32_t ph0 = 0, ph1 = 0;
    int p = 0;
    for (int t = blockIdx.x; t < TILES; t += GRID, p ^= 1) {
        const int c = t >> 5, ch = t & 31;
        const int b0 = ch * BCH;
        const bool has_next = (t + GRID) < TILES;

        // ---- issue next tile into the other buffer ----
        if (has_next && tid == 0) {
            fence_proxy_async_cta();
            const uint32_t mbn = p ? mb0 : mb1;
            mbar_expect_tx(mbn, TILE_BYTES);
            bulk_copy_g2s(sbase + (p ^ 1) * TILE_BYTES,
                          g_uhat4 + (size_t)(t + GRID) * TILE_U4,
                          TILE_BYTES, mbn);
        }

        // ---- stage softmax coefficients as fp16 pairs ----
        if (tid < 96) {
            float c0v, c1v;
            if (it == 0) { c0v = c1v = 1.f / R_; }
            else { c0v = g_c[c * R_ + 2 * tid]; c1v = g_c[c * R_ + 2 * tid + 1]; }
            sch[tid] = __floats2half2_rn(c0v, c1v);
        }

        // ---- wait for current tile ----
        if (p == 0) { mbar_wait(mb0, ph0); ph0 ^= 1; }
        else        { mbar_wait(mb1, ph1); ph1 ^= 1; }
        __syncthreads();   // publish sch; all threads past wait

        const uint32_t sub_base = sbase + p * TILE_BYTES;

        // ---- phase 1: s = c^T * U via mma (warp = (bo-tile, k-half)) ----
        {
            const int mt = warp >> 1;           // 0..7  -> bo 16-block
            const int kh = warp & 1;            // 0..1  -> r half
            const int bo0 = mt * 16;
            const int l = lane & 7, g = lane >> 3;
            // trans blocks: row = r + l (+8 for g>=2), col = bo0 (+8 for odd g)
            uint32_t addr = sub_base +
                (uint32_t)(((kh * 96 + l + ((g & 2) ? 8 : 0)) * 128 +
                            bo0 + (g & 1) * 8) * 2);
            float d[4] = {0.f, 0.f, 0.f, 0.f};
            int kbase = kh * 48 + (lane & 3);
#pragma unroll
            for (int ks = 0; ks < 6; ks++) {
                uint32_t a0, a1, a2, a3;
                ldsm4t(a0, a1, a2, a3, addr);
                uint32_t bb0 = *reinterpret_cast<const uint32_t*>(&sch[kbase]);
                uint32_t bb1 = *reinterpret_cast<const uint32_t*>(&sch[kbase + 4]);
                mma16816(d, a0, a1, a2, a3, bb0, bb1);
                addr += 16 * 128 * 2;
                kbase += 8;
            }
            if ((lane & 3) == 0) {
                sred[kh][bo0 + (lane >> 2)]     = d[0];
                sred[kh][bo0 + (lane >> 2) + 8] = d[2];
            }
        }
        __syncthreads();

        // ---- reduce k-halves + squash (128 threads, tid = bo = b*16+o) ----
        if (tid < 128) {
            float s = sred[0][tid] + sred[1][tid];
            float n2 = s * s;
#pragma unroll
            for (int ofs = 1; ofs < 16; ofs <<= 1)
                n2 += __shfl_xor_sync(0xFFFFFFFFu, n2, ofs);
            float scale = sqrtf(n2) / (1.f + n2);
            s *= scale;
            if (it == 2) {
                out[((size_t)(b0 + (tid >> 4)) * C_ + c) * O_ + (tid & 15)] = s;
            } else {
                float s1 = __shfl_down_sync(0xFFFFFFFFu, s, 1);
                if (!(tid & 1)) sv_h[tid >> 1] = __floats2half2_rn(s, s1);
            }
        }
        __syncthreads();

        // ---- phase 2: a = U * v via mma (warp = r-tile, 12 warps) ----
        if (it != 2 && warp < 12) {
            const int r0 = warp * 16;
            const int l = lane & 7, g = lane >> 3;
            // non-trans blocks: row = r0 + l (+8 for odd g), col (+8 for g>=2)
            uint32_t addr = sub_base +
                (uint32_t)(((r0 + l + (g & 1) * 8) * 128 +
                            ((g & 2) ? 8 : 0)) * 2);
            float d[4] = {0.f, 0.f, 0.f, 0.f};
            const int vb = lane & 3;
#pragma unroll
            for (int ks = 0; ks < 8; ks++) {
                uint32_t a0, a1, a2, a3;
                ldsm4(a0, a1, a2, a3, addr);
                uint32_t bb0 = *reinterpret_cast<const uint32_t*>(&sv_h[ks * 8 + vb]);
                uint32_t bb1 = *reinterpret_cast<const uint32_t*>(&sv_h[ks * 8 + 4 + vb]);
                mma16816(d, a0, a1, a2, a3, bb0, bb1);
                addr += 32;   // +16 halves along bo
            }
            if ((lane & 3) == 0) {
                g_part[it][c][r0 + (lane >> 2)][ch]     = d[0];
                g_part[it][c][r0 + (lane >> 2) + 8][ch] = d[2];
            }
        }
        __syncthreads();   // all reads of buffer p done before its reuse
    }
}

extern "C" void kernel_launch(void* const* d_in, const int* in_sizes, int n_in,
                              void* d_out, int out_size) {
    const float* x = (const float*)d_in[0];  // [B,R,I]
    const float* W = (const float*)d_in[1];  // [R,C,O,I]
    float* out = (float*)d_out;              // [B,C,O]

    const int smem = 2 * TILE_U4 * sizeof(uint4);   // 98304
    cudaFuncSetAttribute(fused_kernel, cudaFuncAttributeMaxDynamicSharedMemorySize, smem);

    convx_kernel<<<R_, 256>>>(x);
    convw_kernel<<<(R_ * C_ * O_) / 256, 256>>>(W);
    uhat_mma_kernel<<<R_ * (C_ / 8), 256>>>();

    for (int it = 0; it < 3; it++) {
        if (it > 0) softmax_kernel<<<C_, 192>>>(it);
        fused_kernel<<<GRID, 512, smem>>>(out, it);
    }
}

// round 12
// speedup vs baseline: 1.8563x; 1.8563x over previous
#include <cuda_runtime.h>
#include <cuda_fp16.h>
#include <stdint.h>

#define B_ 256
#define R_ 192
#define C_ 96
#define O_ 16
#define I_ 20
#define IP 24                   // I padded for mma (zeros)
#define BCH 8                   // batch elements per tile
#define NCH (B_ / BCH)          // 32 chunks
#define TILES (C_ * NCH)        // 3072
#define GRID 304                // persistent CTAs (2/SM on 152 SMs)
#define TILE_U4 (R_ * BCH * O_ / 8)   // 3072 uint4 = 48KB per tile
#define TILE_HALFS (R_ * BCH * O_)    // 24576 halves
#define TILE_BYTES (TILE_U4 * 16)     // 49152

// Scratch (allocation-free rule: __device__ globals)
// u_hat tile-contiguous AND bank-swizzled within each 256B row:
// half-offset(r, chunk, e) = r*128 + (chunk ^ (r&7))*8 + e   (chunk=bo>>3, e=bo&7)
__device__ uint4  g_uhat4[(size_t)TILES * TILE_U4];
__device__ __half g_x16[(size_t)R_ * B_ * IP];        // x fp16 [r][b][24]
__device__ __half g_W16[(size_t)R_ * C_ * O_ * IP];   // W fp16 [r][c][o][24]
__device__ float  g_part[2][C_][R_][NCH];             // agreement partials
__device__ float  g_c[C_ * R_];                       // softmax coefficients [c][r]

// ---- smem addr / TMA bulk / mbarrier helpers ----
__device__ __forceinline__ uint32_t smem_u32(const void* p) {
    return (uint32_t)__cvta_generic_to_shared(p);
}
__device__ __forceinline__ void mbar_init(uint32_t mbar, uint32_t cnt) {
    asm volatile("mbarrier.init.shared.b64 [%0], %1;" :: "r"(mbar), "r"(cnt)
                 : "memory");
}
__device__ __forceinline__ void mbar_expect_tx(uint32_t mbar, uint32_t bytes) {
    asm volatile("mbarrier.arrive.expect_tx.shared.b64 _, [%0], %1;"
                 :: "r"(mbar), "r"(bytes) : "memory");
}
__device__ __forceinline__ void mbar_wait(uint32_t mbar, uint32_t parity) {
    asm volatile(
        "{\n\t.reg .pred P;\n\t"
        "WL%=:\n\t"
        "mbarrier.try_wait.parity.acquire.cta.shared::cta.b64 P, [%0], %1, 0x989680;\n\t"
        "@!P bra WL%=;\n\t}"
        :: "r"(mbar), "r"(parity) : "memory");
}
__device__ __forceinline__ void fence_proxy_async_cta() {
    asm volatile("fence.proxy.async.shared::cta;" ::: "memory");
}
__device__ __forceinline__ void bulk_copy_g2s(uint32_t dst, const void* src,
                                              uint32_t bytes, uint32_t mbar) {
    asm volatile(
        "cp.async.bulk.shared::cta.global.mbarrier::complete_tx::bytes "
        "[%0], [%1], %2, [%3];"
        :: "r"(dst), "l"(src), "r"(bytes), "r"(mbar) : "memory");
}

// ---- ldmatrix helpers ----
__device__ __forceinline__ void ldsm4(uint32_t& r0, uint32_t& r1, uint32_t& r2,
                                      uint32_t& r3, uint32_t addr) {
    asm volatile("ldmatrix.sync.aligned.m8n8.x4.shared.b16 {%0,%1,%2,%3}, [%4];"
                 : "=r"(r0), "=r"(r1), "=r"(r2), "=r"(r3) : "r"(addr));
}
__device__ __forceinline__ void ldsm4t(uint32_t& r0, uint32_t& r1, uint32_t& r2,
                                       uint32_t& r3, uint32_t addr) {
    asm volatile("ldmatrix.sync.aligned.m8n8.x4.trans.shared.b16 {%0,%1,%2,%3}, [%4];"
                 : "=r"(r0), "=r"(r1), "=r"(r2), "=r"(r3) : "r"(addr));
}

// ---- mma helpers (fp16 in, fp32 accum) ----
__device__ __forceinline__ void mma16816(float d[4], uint32_t a0, uint32_t a1,
                                         uint32_t a2, uint32_t a3,
                                         uint32_t b0, uint32_t b1) {
    asm volatile(
        "mma.sync.aligned.m16n8k16.row.col.f32.f16.f16.f32 "
        "{%0,%1,%2,%3},{%4,%5,%6,%7},{%8,%9},{%0,%1,%2,%3};"
        : "+f"(d[0]), "+f"(d[1]), "+f"(d[2]), "+f"(d[3])
        : "r"(a0), "r"(a1), "r"(a2), "r"(a3), "r"(b0), "r"(b1));
}
__device__ __forceinline__ void mma1688(float d[4], uint32_t a0, uint32_t a1,
                                        uint32_t b0) {
    asm volatile(
        "mma.sync.aligned.m16n8k8.row.col.f32.f16.f16.f32 "
        "{%0,%1,%2,%3},{%4,%5},{%6},{%0,%1,%2,%3};"
        : "+f"(d[0]), "+f"(d[1]), "+f"(d[2]), "+f"(d[3])
        : "r"(a0), "r"(a1), "r"(b0));
}

// ============================================================================
// Convert x[b][r][i] f32 -> x16[r][b][24] fp16 (i padded with zeros).
// ============================================================================
__global__ void convx_kernel(const float* __restrict__ x) {
    const int r = blockIdx.x;
    const int b = threadIdx.x;
    const float4* src = reinterpret_cast<const float4*>(x + ((size_t)b * R_ + r) * I_);
    __half2 h[12];
#pragma unroll
    for (int q = 0; q < 5; q++) {
        float4 v = src[q];
        h[2 * q]     = __floats2half2_rn(v.x, v.y);
        h[2 * q + 1] = __floats2half2_rn(v.z, v.w);
    }
    h[10] = __floats2half2_rn(0.f, 0.f);
    h[11] = __floats2half2_rn(0.f, 0.f);
    uint4* dst = reinterpret_cast<uint4*>(g_x16 + ((size_t)r * B_ + b) * IP);
    dst[0] = *reinterpret_cast<uint4*>(&h[0]);
    dst[1] = *reinterpret_cast<uint4*>(&h[4]);
    dst[2] = *reinterpret_cast<uint4*>(&h[8]);
}

// ============================================================================
// Convert W[r][c][o][i] f32 -> W16[r][c][o][24] fp16 (padded).
// ============================================================================
__global__ void convw_kernel(const float* __restrict__ W) {
    const int idx = blockIdx.x * 256 + threadIdx.x;   // (r,c,o) flat, 294912
    const float4* src = reinterpret_cast<const float4*>(W + (size_t)idx * I_);
    __half2 h[12];
#pragma unroll
    for (int q = 0; q < 5; q++) {
        float4 v = src[q];
        h[2 * q]     = __floats2half2_rn(v.x, v.y);
        h[2 * q + 1] = __floats2half2_rn(v.z, v.w);
    }
    h[10] = __floats2half2_rn(0.f, 0.f);
    h[11] = __floats2half2_rn(0.f, 0.f);
    uint4* dst = reinterpret_cast<uint4*>(g_W16 + (size_t)idx * IP);
    dst[0] = *reinterpret_cast<uint4*>(&h[0]);
    dst[1] = *reinterpret_cast<uint4*>(&h[4]);
    dst[2] = *reinterpret_cast<uint4*>(&h[8]);
}

// ============================================================================
// u_hat via tensor cores. Block = (r, 8 c's), 256 threads = 8 warps (1 c each).
// Stores into the swizzled tile layout.
// ============================================================================
__global__ void __launch_bounds__(256) uhat_mma_kernel() {
    const int r  = blockIdx.x / (C_ / 8);
    const int c0 = (blockIdx.x % (C_ / 8)) * 8;
    __shared__ __align__(16) __half xs[B_ * IP];      // [b][24]  12288B
    __shared__ __align__(16) __half ws[8 * O_ * IP];  // [cc][o][24] 6144B
    const int tid = threadIdx.x;
    const int lane = tid & 31, w = tid >> 5;

    {
        const uint4* gx = reinterpret_cast<const uint4*>(g_x16 + (size_t)r * B_ * IP);
        uint4* sx = reinterpret_cast<uint4*>(xs);
#pragma unroll
        for (int m = 0; m < 3; m++) sx[tid + 256 * m] = gx[tid + 256 * m];
        const uint4* gw = reinterpret_cast<const uint4*>(
            g_W16 + ((size_t)r * C_ + c0) * O_ * IP);
        uint4* sw = reinterpret_cast<uint4*>(ws);
        if (tid < 128) { sw[tid] = gw[tid]; sw[tid + 128] = gw[tid + 128]; }
        else { int t = tid - 128; sw[t + 256] = gw[t + 256]; }
    }
    __syncthreads();

    const uint32_t* xs32 = reinterpret_cast<const uint32_t*>(xs);
    const uint32_t* ws32 = reinterpret_cast<const uint32_t*>(ws);
    __half* uh = reinterpret_cast<__half*>(g_uhat4);
    const int rsw = r & 7;   // swizzle factor for this r

    uint32_t bf[2][3];
#pragma unroll
    for (int nt = 0; nt < 2; nt++) {
        int base = (w * 16 + nt * 8 + (lane >> 2)) * 12 + (lane & 3);
        bf[nt][0] = ws32[base];
        bf[nt][1] = ws32[base + 4];
        bf[nt][2] = ws32[base + 8];
    }

    const int c = c0 + w;
#pragma unroll 4
    for (int bt = 0; bt < 16; bt++) {
        const int row = bt * 16 + (lane >> 2);
        const int a0i = row * 12 + (lane & 3);
        const int a1i = a0i + 96;   // row + 8
        uint32_t a0 = xs32[a0i], a1 = xs32[a1i];
        uint32_t a2 = xs32[a0i + 4], a3 = xs32[a1i + 4];
        uint32_t a4 = xs32[a0i + 8], a5 = xs32[a1i + 8];

#pragma unroll
        for (int nt = 0; nt < 2; nt++) {
            float d[4] = {0.f, 0.f, 0.f, 0.f};
            mma16816(d, a0, a1, a2, a3, bf[nt][0], bf[nt][1]);
            mma1688(d, a4, a5, bf[nt][2]);
            __half2 h01 = __floats2half2_rn(d[0], d[1]);
            __half2 h23 = __floats2half2_rn(d[2], d[3]);
            const int e = (lane & 3) * 2;              // within-chunk half offset
            const int blo = row, bhi = row + 8;
            const int chunk = (blo & 7) * 2 + nt;      // same for blo/bhi
            const int csw = (chunk ^ rsw) * 8 + e;
            size_t alo = ((size_t)(c * NCH + (blo >> 3))) * TILE_HALFS
                       + (size_t)r * 128 + csw;
            size_t ahi = ((size_t)(c * NCH + (bhi >> 3))) * TILE_HALFS
                       + (size_t)r * 128 + csw;
            *reinterpret_cast<__half2*>(uh + alo) = h01;
            *reinterpret_cast<__half2*>(uh + ahi) = h23;
        }
    }
}

// ============================================================================
// Softmax over r of accumulated logits -> g_c[c][r]. One block per c.
// ============================================================================
__global__ void softmax_kernel(int it) {
    const int c = blockIdx.x;
    const int tid = threadIdx.x;           // = r
    const int lane = tid & 31, warp = tid >> 5;
    __shared__ float sm[6], ssum[6];

    float lg = 0.f;
    {
        const float4* q0 = reinterpret_cast<const float4*>(&g_part[0][c][tid][0]);
#pragma unroll
        for (int j = 0; j < NCH / 4; j++) {
            float4 v = q0[j];
            lg += v.x + v.y + v.z + v.w;
        }
        if (it == 2) {
            const float4* q1 = reinterpret_cast<const float4*>(&g_part[1][c][tid][0]);
#pragma unroll
            for (int j = 0; j < NCH / 4; j++) {
                float4 v = q1[j];
                lg += v.x + v.y + v.z + v.w;
            }
        }
        lg *= (1.f / B_);
    }

    float m = lg;
#pragma unroll
    for (int ofs = 16; ofs; ofs >>= 1) m = fmaxf(m, __shfl_xor_sync(0xFFFFFFFFu, m, ofs));
    if (lane == 0) sm[warp] = m;
    __syncthreads();
    float mm = sm[0];
#pragma unroll
    for (int w = 1; w < 6; w++) mm = fmaxf(mm, sm[w]);

    float e = expf(lg - mm);
    float s = e;
#pragma unroll
    for (int ofs = 16; ofs; ofs >>= 1) s += __shfl_xor_sync(0xFFFFFFFFu, s, ofs);
    if (lane == 0) ssum[warp] = s;
    __syncthreads();
    float tot = 0.f;
#pragma unroll
    for (int w = 0; w < 6; w++) tot += ssum[w];

    g_c[c * R_ + tid] = e / tot;
}

// ============================================================================
// Persistent fused routing kernel. 304 CTAs x 512 threads, double-buffered
// 48KB swizzled tiles via cp.async.bulk. Phases 1 & 2 on tensor cores with
// conflict-free ldmatrix (row&7 == lane&7 => distinct bank groups).
// ============================================================================
__global__ void __launch_bounds__(512, 2) fused_kernel(float* __restrict__ out, int it) {
    extern __shared__ __align__(16) uint4 su4[];   // 2 * TILE_U4
    __shared__ float   sred[2][128];               // per-k-half s partials
    __shared__ __half2 sv_h[64];                   // v fp16 pairs [bo/2]
    __shared__ __half2 sch[96];                    // c fp16 pairs [r/2]
    __shared__ __align__(8) uint64_t mbars[2];

    const int tid = threadIdx.x;
    const int lane = tid & 31, warp = tid >> 5;    // 16 warps
    const uint32_t mb0 = smem_u32(&mbars[0]);
    const uint32_t mb1 = smem_u32(&mbars[1]);
    const uint32_t sbase = smem_u32(su4);

    if (tid == 0) {
        mbar_init(mb0, 1);
        mbar_init(mb1, 1);
        fence_proxy_async_cta();
    }
    __syncthreads();

    // ---- prologue: issue first tile into buffer 0 ----
    if (tid == 0) {
        mbar_expect_tx(mb0, TILE_BYTES);
        bulk_copy_g2s(sbase, g_uhat4 + (size_t)blockIdx.x * TILE_U4,
                      TILE_BYTES, mb0);
    }

    uint32_t ph0 = 0, ph1 = 0;
    int p = 0;
    for (int t = blockIdx.x; t < TILES; t += GRID, p ^= 1) {
        const int c = t >> 5, ch = t & 31;
        const int b0 = ch * BCH;
        const bool has_next = (t + GRID) < TILES;

        // ---- issue next tile into the other buffer ----
        if (has_next && tid == 0) {
            fence_proxy_async_cta();
            const uint32_t mbn = p ? mb0 : mb1;
            mbar_expect_tx(mbn, TILE_BYTES);
            bulk_copy_g2s(sbase + (p ^ 1) * TILE_BYTES,
                          g_uhat4 + (size_t)(t + GRID) * TILE_U4,
                          TILE_BYTES, mbn);
        }

        // ---- stage softmax coefficients as fp16 pairs ----
        if (tid < 96) {
            float c0v, c1v;
            if (it == 0) { c0v = c1v = 1.f / R_; }
            else { c0v = g_c[c * R_ + 2 * tid]; c1v = g_c[c * R_ + 2 * tid + 1]; }
            sch[tid] = __floats2half2_rn(c0v, c1v);
        }

        // ---- wait for current tile ----
        if (p == 0) { mbar_wait(mb0, ph0); ph0 ^= 1; }
        else        { mbar_wait(mb1, ph1); ph1 ^= 1; }
        __syncthreads();   // publish sch; all threads past wait

        const uint32_t sub_base = sbase + p * TILE_BYTES;

        // ---- phase 1: s = c^T * U via mma (warp = (bo-tile, k-half)) ----
        // trans matrices: rows = r (swizzle factor r&7 == l), col chunk fixed.
        {
            const int mt = warp >> 1;           // 0..7  -> bo 16-block
            const int kh = warp & 1;            // 0..1  -> r half
            const int bo0 = mt * 16;
            const int l = lane & 7, g = lane >> 3;
            const int chunk = (bo0 >> 3) + (g & 1);      // 16B chunk index
            const int row0 = kh * 96 + l + ((g & 2) ? 8 : 0);
            uint32_t addr = sub_base +
                (uint32_t)((row0 * 128 + ((chunk ^ l) * 8)) * 2);
            float d[4] = {0.f, 0.f, 0.f, 0.f};
            int kbase = kh * 48 + (lane & 3);
#pragma unroll
            for (int ks = 0; ks < 6; ks++) {
                uint32_t a0, a1, a2, a3;
                ldsm4t(a0, a1, a2, a3, addr);
                uint32_t bb0 = *reinterpret_cast<const uint32_t*>(&sch[kbase]);
                uint32_t bb1 = *reinterpret_cast<const uint32_t*>(&sch[kbase + 4]);
                mma16816(d, a0, a1, a2, a3, bb0, bb1);
                addr += 16 * 128 * 2;   // +16 r rows (swizzle factor unchanged)
                kbase += 8;
            }
            if ((lane & 3) == 0) {
                sred[kh][bo0 + (lane >> 2)]     = d[0];
                sred[kh][bo0 + (lane >> 2) + 8] = d[2];
            }
        }
        __syncthreads();

        // ---- reduce k-halves + squash (128 threads, tid = bo = b*16+o) ----
        if (tid < 128) {
            float s = sred[0][tid] + sred[1][tid];
            float n2 = s * s;
#pragma unroll
            for (int ofs = 1; ofs < 16; ofs <<= 1)
                n2 += __shfl_xor_sync(0xFFFFFFFFu, n2, ofs);
            float scale = sqrtf(n2) / (1.f + n2);
            s *= scale;
            if (it == 2) {
                out[((size_t)(b0 + (tid >> 4)) * C_ + c) * O_ + (tid & 15)] = s;
            } else {
                float s1 = __shfl_down_sync(0xFFFFFFFFu, s, 1);
                if (!(tid & 1)) sv_h[tid >> 1] = __floats2half2_rn(s, s1);
            }
        }
        __syncthreads();

        // ---- phase 2: a = U * v via mma (warp = r-tile, 12 warps) ----
        // non-trans matrices: rows = r (swizzle factor r&7 == l).
        if (it != 2 && warp < 12) {
            const int r0 = warp * 16;
            const int l = lane & 7, g = lane >> 3;
            const int row = r0 + l + ((g & 1) ? 8 : 0);
            const uint32_t rowb = sub_base + (uint32_t)(row * 256);
            const int cq0 = (g & 2) ? 1 : 0;
            float d[4] = {0.f, 0.f, 0.f, 0.f};
            const int vb = lane & 3;
#pragma unroll
            for (int ks = 0; ks < 8; ks++) {
                uint32_t a0, a1, a2, a3;
                uint32_t addr = rowb + (uint32_t)((((2 * ks + cq0) ^ l) * 8) * 2);
                ldsm4(a0, a1, a2, a3, addr);
                uint32_t bb0 = *reinterpret_cast<const uint32_t*>(&sv_h[ks * 8 + vb]);
                uint32_t bb1 = *reinterpret_cast<const uint32_t*>(&sv_h[ks * 8 + 4 + vb]);
                mma16816(d, a0, a1, a2, a3, bb0, bb1);
            }
            if ((lane & 3) == 0) {
                g_part[it][c][r0 + (lane >> 2)][ch]     = d[0];
                g_part[it][c][r0 + (lane >> 2) + 8][ch] = d[2];
            }
        }
        __syncthreads();   // all reads of buffer p done before its reuse
    }
}

extern "C" void kernel_launch(void* const* d_in, const int* in_sizes, int n_in,
                              void* d_out, int out_size) {
    const float* x = (const float*)d_in[0];  // [B,R,I]
    const float* W = (const float*)d_in[1];  // [R,C,O,I]
    float* out = (float*)d_out;              // [B,C,O]

    const int smem = 2 * TILE_U4 * sizeof(uint4);   // 98304
    cudaFuncSetAttribute(fused_kernel, cudaFuncAttributeMaxDynamicSharedMemorySize, smem);

    convx_kernel<<<R_, 256>>>(x);
    convw_kernel<<<(R_ * C_ * O_) / 256, 256>>>(W);
    uhat_mma_kernel<<<R_ * (C_ / 8), 256>>>();

    for (int it = 0; it < 3; it++) {
        if (it > 0) softmax_kernel<<<C_, 192>>>(it);
        fused_kernel<<<GRID, 512, smem>>>(out, it);
    }
}

// round 13
// speedup vs baseline: 2.0985x; 1.1305x over previous
#include <cuda_runtime.h>
#include <cuda_fp16.h>
#include <stdint.h>

#define B_ 256
#define R_ 192
#define C_ 96
#define O_ 16
#define I_ 20
#define IP 24                   // I padded for mma (zeros)
#define BCH 8                   // batch elements per tile
#define NCH (B_ / BCH)          // 32 chunks
#define TILES (C_ * NCH)        // 3072
#define GRID 304                // persistent CTAs (2/SM on 152 SMs)
#define TILE_U4 (R_ * BCH * O_ / 8)   // 3072 uint4 = 48KB per tile
#define TILE_HALFS (R_ * BCH * O_)    // 24576 halves
#define TILE_BYTES (TILE_U4 * 16)     // 49152

// Scratch (allocation-free rule: __device__ globals)
// u_hat tile-contiguous AND bank-swizzled within each 256B row:
// half-offset(r, chunk, e) = r*128 + (chunk ^ (r&7))*8 + e   (chunk=bo>>3, e=bo&7)
__device__ uint4  g_uhat4[(size_t)TILES * TILE_U4];
__device__ __half g_x16[(size_t)R_ * B_ * IP];        // x fp16 [r][b][24]
__device__ __half g_W16[(size_t)R_ * C_ * O_ * IP];   // W fp16 [r][c][o][24]
__device__ float  g_part[2][C_][R_][NCH];             // agreement partials
__device__ float  g_c[C_ * R_];                       // softmax coefficients [c][r]

// ---- smem addr / TMA bulk / mbarrier helpers ----
__device__ __forceinline__ uint32_t smem_u32(const void* p) {
    return (uint32_t)__cvta_generic_to_shared(p);
}
__device__ __forceinline__ void mbar_init(uint32_t mbar, uint32_t cnt) {
    asm volatile("mbarrier.init.shared.b64 [%0], %1;" :: "r"(mbar), "r"(cnt)
                 : "memory");
}
__device__ __forceinline__ void mbar_expect_tx(uint32_t mbar, uint32_t bytes) {
    asm volatile("mbarrier.arrive.expect_tx.shared.b64 _, [%0], %1;"
                 :: "r"(mbar), "r"(bytes) : "memory");
}
__device__ __forceinline__ void mbar_wait(uint32_t mbar, uint32_t parity) {
    asm volatile(
        "{\n\t.reg .pred P;\n\t"
        "WL%=:\n\t"
        "mbarrier.try_wait.parity.acquire.cta.shared::cta.b64 P, [%0], %1, 0x989680;\n\t"
        "@!P bra WL%=;\n\t}"
        :: "r"(mbar), "r"(parity) : "memory");
}
__device__ __forceinline__ void fence_proxy_async_cta() {
    asm volatile("fence.proxy.async.shared::cta;" ::: "memory");
}
__device__ __forceinline__ void bulk_copy_g2s(uint32_t dst, const void* src,
                                              uint32_t bytes, uint32_t mbar) {
    asm volatile(
        "cp.async.bulk.shared::cta.global.mbarrier::complete_tx::bytes "
        "[%0], [%1], %2, [%3];"
        :: "r"(dst), "l"(src), "r"(bytes), "r"(mbar) : "memory");
}

// ---- ldmatrix helpers ----
__device__ __forceinline__ void ldsm4(uint32_t& r0, uint32_t& r1, uint32_t& r2,
                                      uint32_t& r3, uint32_t addr) {
    asm volatile("ldmatrix.sync.aligned.m8n8.x4.shared.b16 {%0,%1,%2,%3}, [%4];"
                 : "=r"(r0), "=r"(r1), "=r"(r2), "=r"(r3) : "r"(addr));
}
__device__ __forceinline__ void ldsm4t(uint32_t& r0, uint32_t& r1, uint32_t& r2,
                                       uint32_t& r3, uint32_t addr) {
    asm volatile("ldmatrix.sync.aligned.m8n8.x4.trans.shared.b16 {%0,%1,%2,%3}, [%4];"
                 : "=r"(r0), "=r"(r1), "=r"(r2), "=r"(r3) : "r"(addr));
}

// ---- mma helpers (fp16 in, fp32 accum) ----
__device__ __forceinline__ void mma16816(float d[4], uint32_t a0, uint32_t a1,
                                         uint32_t a2, uint32_t a3,
                                         uint32_t b0, uint32_t b1) {
    asm volatile(
        "mma.sync.aligned.m16n8k16.row.col.f32.f16.f16.f32 "
        "{%0,%1,%2,%3},{%4,%5,%6,%7},{%8,%9},{%0,%1,%2,%3};"
        : "+f"(d[0]), "+f"(d[1]), "+f"(d[2]), "+f"(d[3])
        : "r"(a0), "r"(a1), "r"(a2), "r"(a3), "r"(b0), "r"(b1));
}
__device__ __forceinline__ void mma1688(float d[4], uint32_t a0, uint32_t a1,
                                        uint32_t b0) {
    asm volatile(
        "mma.sync.aligned.m16n8k8.row.col.f32.f16.f16.f32 "
        "{%0,%1,%2,%3},{%4,%5},{%6},{%0,%1,%2,%3};"
        : "+f"(d[0]), "+f"(d[1]), "+f"(d[2]), "+f"(d[3])
        : "r"(a0), "r"(a1), "r"(b0));
}

// ============================================================================
// Convert x[b][r][i] f32 -> x16[r][b][24] fp16 (i padded with zeros).
// ============================================================================
__global__ void convx_kernel(const float* __restrict__ x) {
    const int r = blockIdx.x;
    const int b = threadIdx.x;
    const float4* src = reinterpret_cast<const float4*>(x + ((size_t)b * R_ + r) * I_);
    __half2 h[12];
#pragma unroll
    for (int q = 0; q < 5; q++) {
        float4 v = src[q];
        h[2 * q]     = __floats2half2_rn(v.x, v.y);
        h[2 * q + 1] = __floats2half2_rn(v.z, v.w);
    }
    h[10] = __floats2half2_rn(0.f, 0.f);
    h[11] = __floats2half2_rn(0.f, 0.f);
    uint4* dst = reinterpret_cast<uint4*>(g_x16 + ((size_t)r * B_ + b) * IP);
    dst[0] = *reinterpret_cast<uint4*>(&h[0]);
    dst[1] = *reinterpret_cast<uint4*>(&h[4]);
    dst[2] = *reinterpret_cast<uint4*>(&h[8]);
}

// ============================================================================
// Convert W[r][c][o][i] f32 -> W16[r][c][o][24] fp16 (padded).
// ============================================================================
__global__ void convw_kernel(const float* __restrict__ W) {
    const int idx = blockIdx.x * 256 + threadIdx.x;   // (r,c,o) flat, 294912
    const float4* src = reinterpret_cast<const float4*>(W + (size_t)idx * I_);
    __half2 h[12];
#pragma unroll
    for (int q = 0; q < 5; q++) {
        float4 v = src[q];
        h[2 * q]     = __floats2half2_rn(v.x, v.y);
        h[2 * q + 1] = __floats2half2_rn(v.z, v.w);
    }
    h[10] = __floats2half2_rn(0.f, 0.f);
    h[11] = __floats2half2_rn(0.f, 0.f);
    uint4* dst = reinterpret_cast<uint4*>(g_W16 + (size_t)idx * IP);
    dst[0] = *reinterpret_cast<uint4*>(&h[0]);
    dst[1] = *reinterpret_cast<uint4*>(&h[4]);
    dst[2] = *reinterpret_cast<uint4*>(&h[8]);
}

// ============================================================================
// u_hat via tensor cores. Block = (r, 8 c's), 256 threads = 8 warps (1 c each).
// D blocks staged in smem (double-buffered) then written out as contiguous
// 256B rows (full 128B store transactions into the swizzled tile layout).
// ============================================================================
__global__ void __launch_bounds__(256) uhat_mma_kernel() {
    const int r  = blockIdx.x / (C_ / 8);
    const int c0 = (blockIdx.x % (C_ / 8)) * 8;
    __shared__ __align__(16) __half xs[B_ * IP];        // 12288B
    __shared__ __align__(16) __half ws[8 * O_ * IP];    // 6144B
    __shared__ __align__(16) __half sd[2][8][16][16];   // stage, 8192B
    const int tid = threadIdx.x;
    const int lane = tid & 31, w = tid >> 5;

    {
        const uint4* gx = reinterpret_cast<const uint4*>(g_x16 + (size_t)r * B_ * IP);
        uint4* sx = reinterpret_cast<uint4*>(xs);
#pragma unroll
        for (int m = 0; m < 3; m++) sx[tid + 256 * m] = gx[tid + 256 * m];
        const uint4* gw = reinterpret_cast<const uint4*>(
            g_W16 + ((size_t)r * C_ + c0) * O_ * IP);
        uint4* sw = reinterpret_cast<uint4*>(ws);
        if (tid < 128) { sw[tid] = gw[tid]; sw[tid + 128] = gw[tid + 128]; }
        else { int t = tid - 128; sw[t + 256] = gw[t + 256]; }
    }
    __syncthreads();

    const uint32_t* xs32 = reinterpret_cast<const uint32_t*>(xs);
    const uint32_t* ws32 = reinterpret_cast<const uint32_t*>(ws);
    __half* uh = reinterpret_cast<__half*>(g_uhat4);
    const int rsw = r & 7;   // swizzle factor for this r

    uint32_t bf[2][3];
#pragma unroll
    for (int nt = 0; nt < 2; nt++) {
        int base = (w * 16 + nt * 8 + (lane >> 2)) * 12 + (lane & 3);
        bf[nt][0] = ws32[base];
        bf[nt][1] = ws32[base + 4];
        bf[nt][2] = ws32[base + 8];
    }

#pragma unroll 2
    for (int bt = 0; bt < 16; bt++) {
        const int row = bt * 16 + (lane >> 2);
        const int a0i = row * 12 + (lane & 3);
        const int a1i = a0i + 96;   // row + 8
        uint32_t a0 = xs32[a0i], a1 = xs32[a1i];
        uint32_t a2 = xs32[a0i + 4], a3 = xs32[a1i + 4];
        uint32_t a4 = xs32[a0i + 8], a5 = xs32[a1i + 8];

        __half* sdb = &sd[bt & 1][w][0][0];
#pragma unroll
        for (int nt = 0; nt < 2; nt++) {
            float d[4] = {0.f, 0.f, 0.f, 0.f};
            mma16816(d, a0, a1, a2, a3, bf[nt][0], bf[nt][1]);
            mma1688(d, a4, a5, bf[nt][2]);
            const int col = nt * 8 + (lane & 3) * 2;
            const int rlo = lane >> 2;
            *reinterpret_cast<__half2*>(sdb + rlo * 16 + col)
                = __floats2half2_rn(d[0], d[1]);
            *reinterpret_cast<__half2*>(sdb + (rlo + 8) * 16 + col)
                = __floats2half2_rn(d[2], d[3]);
        }
        __syncthreads();   // stage complete (also: prior copy of bt-1 done)

        // copy out: thread = (cc = tid>>5, idx = tid&31)
        {
            const int cc = tid >> 5, idx = tid & 31;
            const int b_loc = idx >> 1, hsel = idx & 1;
            const int b_glob = bt * 16 + b_loc;
            const int ch = b_glob >> 3, bl = b_glob & 7;
            const int csw = ((bl * 2 + hsel) ^ rsw) * 8;
            uint4 val = *reinterpret_cast<const uint4*>(
                &sd[bt & 1][cc][b_loc][hsel * 8]);
            size_t off = ((size_t)((c0 + cc) * NCH + ch)) * TILE_HALFS
                       + (size_t)r * 128 + csw;
            *reinterpret_cast<uint4*>(uh + off) = val;
        }
    }
}

// ============================================================================
// Softmax over r of accumulated logits -> g_c[c][r]. One block per c.
// ============================================================================
__global__ void softmax_kernel(int it) {
    const int c = blockIdx.x;
    const int tid = threadIdx.x;           // = r
    const int lane = tid & 31, warp = tid >> 5;
    __shared__ float sm[6], ssum[6];

    float lg = 0.f;
    {
        const float4* q0 = reinterpret_cast<const float4*>(&g_part[0][c][tid][0]);
#pragma unroll
        for (int j = 0; j < NCH / 4; j++) {
            float4 v = q0[j];
            lg += v.x + v.y + v.z + v.w;
        }
        if (it == 2) {
            const float4* q1 = reinterpret_cast<const float4*>(&g_part[1][c][tid][0]);
#pragma unroll
            for (int j = 0; j < NCH / 4; j++) {
                float4 v = q1[j];
                lg += v.x + v.y + v.z + v.w;
            }
        }
        lg *= (1.f / B_);
    }

    float m = lg;
#pragma unroll
    for (int ofs = 16; ofs; ofs >>= 1) m = fmaxf(m, __shfl_xor_sync(0xFFFFFFFFu, m, ofs));
    if (lane == 0) sm[warp] = m;
    __syncthreads();
    float mm = sm[0];
#pragma unroll
    for (int w = 1; w < 6; w++) mm = fmaxf(mm, sm[w]);

    float e = expf(lg - mm);
    float s = e;
#pragma unroll
    for (int ofs = 16; ofs; ofs >>= 1) s += __shfl_xor_sync(0xFFFFFFFFu, s, ofs);
    if (lane == 0) ssum[warp] = s;
    __syncthreads();
    float tot = 0.f;
#pragma unroll
    for (int w = 0; w < 6; w++) tot += ssum[w];

    g_c[c * R_ + tid] = e / tot;
}

// ============================================================================
// Persistent fused routing kernel. 304 CTAs x 512 threads, double-buffered
// 48KB swizzled tiles via cp.async.bulk. Phases on tensor cores.
// SERPENTINE tile order: odd iterations traverse tiles in reverse, so each
// launch re-reads the previous launch's most-recently-touched tiles first
// (L2 reuse across launches; partial sums are order-independent).
// ============================================================================
__global__ void __launch_bounds__(512, 2) fused_kernel(float* __restrict__ out, int it) {
    extern __shared__ __align__(16) uint4 su4[];   // 2 * TILE_U4
    __shared__ float   sred[2][128];               // per-k-half s partials
    __shared__ __half2 sv_h[64];                   // v fp16 pairs [bo/2]
    __shared__ __half2 sch[96];                    // c fp16 pairs [r/2]
    __shared__ __align__(8) uint64_t mbars[2];

    const int tid = threadIdx.x;
    const int lane = tid & 31, warp = tid >> 5;    // 16 warps
    const uint32_t mb0 = smem_u32(&mbars[0]);
    const uint32_t mb1 = smem_u32(&mbars[1]);
    const uint32_t sbase = smem_u32(su4);
    const bool rev = (it & 1) != 0;

    if (tid == 0) {
        mbar_init(mb0, 1);
        mbar_init(mb1, 1);
        fence_proxy_async_cta();
    }
    __syncthreads();

    // ---- prologue: issue first tile into buffer 0 ----
    if (tid == 0) {
        const int t0 = rev ? (TILES - 1 - blockIdx.x) : blockIdx.x;
        mbar_expect_tx(mb0, TILE_BYTES);
        bulk_copy_g2s(sbase, g_uhat4 + (size_t)t0 * TILE_U4, TILE_BYTES, mb0);
    }

    uint32_t ph0 = 0, ph1 = 0;
    int p = 0;
    for (int lin = blockIdx.x; lin < TILES; lin += GRID, p ^= 1) {
        const int t = rev ? (TILES - 1 - lin) : lin;
        const int c = t >> 5, ch = t & 31;
        const int b0 = ch * BCH;
        const bool has_next = (lin + GRID) < TILES;

        // ---- issue next tile into the other buffer ----
        if (has_next && tid == 0) {
            fence_proxy_async_cta();
            const int tn = rev ? (TILES - 1 - (lin + GRID)) : (lin + GRID);
            const uint32_t mbn = p ? mb0 : mb1;
            mbar_expect_tx(mbn, TILE_BYTES);
            bulk_copy_g2s(sbase + (p ^ 1) * TILE_BYTES,
                          g_uhat4 + (size_t)tn * TILE_U4, TILE_BYTES, mbn);
        }

        // ---- stage softmax coefficients as fp16 pairs ----
        if (tid < 96) {
            float c0v, c1v;
            if (it == 0) { c0v = c1v = 1.f / R_; }
            else { c0v = g_c[c * R_ + 2 * tid]; c1v = g_c[c * R_ + 2 * tid + 1]; }
            sch[tid] = __floats2half2_rn(c0v, c1v);
        }

        // ---- wait for current tile ----
        if (p == 0) { mbar_wait(mb0, ph0); ph0 ^= 1; }
        else        { mbar_wait(mb1, ph1); ph1 ^= 1; }
        __syncthreads();   // publish sch; all threads past wait

        const uint32_t sub_base = sbase + p * TILE_BYTES;

        // ---- phase 1: s = c^T * U via mma (warp = (bo-tile, k-half)) ----
        {
            const int mt = warp >> 1;           // 0..7  -> bo 16-block
            const int kh = warp & 1;            // 0..1  -> r half
            const int bo0 = mt * 16;
            const int l = lane & 7, g = lane >> 3;
            const int chunk = (bo0 >> 3) + (g & 1);      // 16B chunk index
            const int row0 = kh * 96 + l + ((g & 2) ? 8 : 0);
            uint32_t addr = sub_base +
                (uint32_t)((row0 * 128 + ((chunk ^ l) * 8)) * 2);
            float d[4] = {0.f, 0.f, 0.f, 0.f};
            int kbase = kh * 48 + (lane & 3);
#pragma unroll
            for (int ks = 0; ks < 6; ks++) {
                uint32_t a0, a1, a2, a3;
                ldsm4t(a0, a1, a2, a3, addr);
                uint32_t bb0 = *reinterpret_cast<const uint32_t*>(&sch[kbase]);
                uint32_t bb1 = *reinterpret_cast<const uint32_t*>(&sch[kbase + 4]);
                mma16816(d, a0, a1, a2, a3, bb0, bb1);
                addr += 16 * 128 * 2;   // +16 r rows (swizzle factor unchanged)
                kbase += 8;
            }
            if ((lane & 3) == 0) {
                sred[kh][bo0 + (lane >> 2)]     = d[0];
                sred[kh][bo0 + (lane >> 2) + 8] = d[2];
            }
        }
        __syncthreads();

        // ---- reduce k-halves + squash (128 threads, tid = bo = b*16+o) ----
        if (tid < 128) {
            float s = sred[0][tid] + sred[1][tid];
            float n2 = s * s;
#pragma unroll
            for (int ofs = 1; ofs < 16; ofs <<= 1)
                n2 += __shfl_xor_sync(0xFFFFFFFFu, n2, ofs);
            float scale = sqrtf(n2) / (1.f + n2);
            s *= scale;
            if (it == 2) {
                out[((size_t)(b0 + (tid >> 4)) * C_ + c) * O_ + (tid & 15)] = s;
            } else {
                float s1 = __shfl_down_sync(0xFFFFFFFFu, s, 1);
                if (!(tid & 1)) sv_h[tid >> 1] = __floats2half2_rn(s, s1);
            }
        }
        __syncthreads();

        // ---- phase 2: a = U * v via mma (warp = r-tile, 12 warps) ----
        if (it != 2 && warp < 12) {
            const int r0 = warp * 16;
            const int l = lane & 7, g = lane >> 3;
            const int row = r0 + l + ((g & 1) ? 8 : 0);
            const uint32_t rowb = sub_base + (uint32_t)(row * 256);
            const int cq0 = (g & 2) ? 1 : 0;
            float d[4] = {0.f, 0.f, 0.f, 0.f};
            const int vb = lane & 3;
#pragma unroll
            for (int ks = 0; ks < 8; ks++) {
                uint32_t a0, a1, a2, a3;
                uint32_t addr = rowb + (uint32_t)((((2 * ks + cq0) ^ l) * 8) * 2);
                ldsm4(a0, a1, a2, a3, addr);
                uint32_t bb0 = *reinterpret_cast<const uint32_t*>(&sv_h[ks * 8 + vb]);
                uint32_t bb1 = *reinterpret_cast<const uint32_t*>(&sv_h[ks * 8 + 4 + vb]);
                mma16816(d, a0, a1, a2, a3, bb0, bb1);
            }
            if ((lane & 3) == 0) {
                g_part[it][c][r0 + (lane >> 2)][ch]     = d[0];
                g_part[it][c][r0 + (lane >> 2) + 8][ch] = d[2];
            }
        }
        __syncthreads();   // all reads of buffer p done before its reuse
    }
}

extern "C" void kernel_launch(void* const* d_in, const int* in_sizes, int n_in,
                              void* d_out, int out_size) {
    const float* x = (const float*)d_in[0];  // [B,R,I]
    const float* W = (const float*)d_in[1];  // [R,C,O,I]
    float* out = (float*)d_out;              // [B,C,O]

    const int smem = 2 * TILE_U4 * sizeof(uint4);   // 98304
    cudaFuncSetAttribute(fused_kernel, cudaFuncAttributeMaxDynamicSharedMemorySize, smem);

    convx_kernel<<<R_, 256>>>(x);
    convw_kernel<<<(R_ * C_ * O_) / 256, 256>>>(W);
    uhat_mma_kernel<<<R_ * (C_ / 8), 256>>>();

    for (int it = 0; it < 3; it++) {
        if (it > 0) softmax_kernel<<<C_, 192>>>(it);
        fused_kernel<<<GRID, 512, smem>>>(out, it);
    }
}